// round 13
// baseline (speedup 1.0000x reference)
#include <cuda_runtime.h>
#include <cuda_fp16.h>

// ---------------- problem constants ----------------
#define NBATCH 65536
#define NNODE  10
#define KD     512
#define HD     64
#define NC     128
#define MROWS  (NBATCH * NNODE)            // 655360
#define BPC    12                          // batches per CTA
#define RPC    120                         // valid rows per CTA
#define NCTA   ((NBATCH + BPC - 1) / BPC)  // 5462
#define NCHUNK 16                          // K chunks of 32
#define NH     32                          // k16 halves
#define NPAIR  8                           // chunk pairs per tile

// W1 -> fp16, layout [k_phys][n] with k16-slot permutation baked in (see convB).
__device__ __align__(128) __half g_Bh[KD * NC];

__constant__ int c_I[45] = {0,0,0,0,0,0,0,0,0, 1,1,1,1,1,1,1,1, 2,2,2,2,2,2,2,
                            3,3,3,3,3,3, 4,4,4,4,4, 5,5,5,5, 6,6,6, 7,7, 8};
__constant__ int c_J[45] = {1,2,3,4,5,6,7,8,9, 2,3,4,5,6,7,8,9, 3,4,5,6,7,8,9,
                            4,5,6,7,8,9, 5,6,7,8,9, 6,7,8,9, 7,8,9, 8,9, 9};

// ---------------- smem layout (dynamic) ----------------
// [0:256) sb1 ; [256:512) sw2 ; [512:516) b2
// [1024 : +4*8704) B stages (4, chunk&3)
// epilogue OVERLAY from 1024: sp f32 [128][132], then vbuf[540]
#define OFF_SB1   0
#define OFF_SW2   256
#define OFF_SB2   512
#define OFF_BSTG  1024
#define BROW      272
#define STAGE_SZ  (32 * BROW)              // 8704
#define OFF_SP    1024
#define SP_STRIDE 132
#define OFF_VBUF  (OFF_SP + 128 * SP_STRIDE * 4)  // 68608
#define SMEM_BYTES (OFF_VBUF + 540 * 4 + 16)      // 70784  (B stages end at 35840)

__device__ __forceinline__ unsigned smem_u32(const void* p) {
    unsigned a;
    asm("{ .reg .u64 t; cvta.to.shared.u64 t, %1; cvt.u32.u64 %0, t; }" : "=r"(a) : "l"(p));
    return a;
}
__device__ __forceinline__ void cp16(unsigned dst, const void* src) {
    asm volatile("cp.async.cg.shared.global [%0], [%1], 16;" :: "r"(dst), "l"(src) : "memory");
}
#define CP_COMMIT() asm volatile("cp.async.commit_group;" ::: "memory")
#define CP_WAIT0()  asm volatile("cp.async.wait_group 0;" ::: "memory")

#define LDMX4T(r0, r1, r2, r3, addr) \
    asm volatile("ldmatrix.sync.aligned.m8n8.x4.trans.shared.b16 {%0,%1,%2,%3}, [%4];" \
                 : "=r"(r0), "=r"(r1), "=r"(r2), "=r"(r3) : "r"(addr))

#define MMA16816(d, a0, a1, a2, a3, b0, b1) \
    asm volatile("mma.sync.aligned.m16n8k16.row.col.f32.f16.f16.f32 " \
                 "{%0,%1,%2,%3},{%4,%5,%6,%7},{%8,%9},{%0,%1,%2,%3};" \
                 : "+f"((d)[0]), "+f"((d)[1]), "+f"((d)[2]), "+f"((d)[3]) \
                 : "r"(a0), "r"(a1), "r"(a2), "r"(a3), "r"(b0), "r"(b1))

// streaming LDG.128 (evict-first): X has zero reuse
__device__ __forceinline__ float4 ldg128_cs(const void* p) {
    float4 v;
    asm volatile("ld.global.cs.v4.f32 {%0,%1,%2,%3}, [%4];"
                 : "=f"(v.x), "=f"(v.y), "=f"(v.z), "=f"(v.w) : "l"(p));
    return v;
}

// ---------------- kernel 0: W1 -> fp16, [k][n], with k16 permutation ----------------
// A is loaded as float4 at col 4*tig: logical ks (4t..4t+3) occupy mma k-slots
// (2t, 2t+1, 2t+8, 2t+9). B rows stored in matching slot order.
__global__ void convB_kernel(const float* __restrict__ W1) {
    int idx = blockIdx.x * 256 + threadIdx.x;      // logical k*128 + n
    if (idx >= KD * NC) return;
    int k = idx >> 7, n = idx & 127;
    float w = W1[((long long)k + (n >= HD ? KD : 0)) * HD + (n & (HD - 1))];
    int kk = k & 15, t = kk >> 2, d = kk & 3;
    int phys = (k & ~15) + t * 2 + (d & 1) + ((d >= 2) ? 8 : 0);
    g_Bh[phys * NC + n] = __float2half_rn(w);
}

// ---------------- fused GEMM (4-stage B, one barrier per chunk-PAIR) ----------------
__global__ __launch_bounds__(256, 2)
void gemm_pair_kernel(const float* __restrict__ X,
                      const float* __restrict__ b1, const float* __restrict__ W2,
                      const float* __restrict__ b2, float* __restrict__ out) {
    extern __shared__ char smem[];
    const unsigned sb = smem_u32(smem);
    const int tid  = threadIdx.x;
    const int warp = tid >> 5;
    const int lane = tid & 31;
    const int wm   = warp & 3;      // 4 M-groups of 32 rows
    const int wn   = warp >> 2;     // 2 N-groups of 64 cols
    const int gid  = lane >> 2;     // 0..7
    const int tig  = lane & 3;      // 0..3
    const long long tile = blockIdx.x;

    if (tid < HD) {
        ((float*)(smem + OFF_SB1))[tid] = b1[tid];
        ((float*)(smem + OFF_SW2))[tid] = W2[tid];
    }
    if (tid == 0) ((float*)(smem + OFF_SB2))[0] = b2[0];

    // ---- A byte offsets (32-bit: X is 1.34GB < 4GB): rows r, r+8, r+16, r+24 ----
    unsigned offs[4];
    {
        long long r0 = tile * RPC + wm * 32 + gid;
        #pragma unroll
        for (int q = 0; q < 4; q++) {
            long long rr = r0 + q * 8;
            if (rr >= MROWS) rr = MROWS - 1;       // per-row tail clamp (rows unused)
            offs[q] = (unsigned)((rr * KD + 4 * tig) * 4);
        }
    }
    const char* Xb = (const char*)X;

    // ---- B cp.async coordinates ----
    const int bk = tid >> 3;                 // 0..31 (phys k row in chunk)
    const int bg = tid & 7;
    const unsigned bdst0 = (unsigned)(bk * BROW + bg * 16);
    const __half* bsrc = g_Bh + bk * NC + bg * 8;

    auto issueB = [&](int c) {   // stage chunk c into buffer c&3
        const unsigned stg = sb + OFF_BSTG + (unsigned)(c & 3) * STAGE_SZ;
        const __half* src = bsrc + c * 32 * NC;
        cp16(stg + bdst0,       src);
        cp16(stg + bdst0 + 128, src + 64);
    };

    // ---- ldmatrix lane address (within stage) ----
    const unsigned sel   = lane >> 3;
    const unsigned rowin = lane & 7;
    const unsigned ldm_l = ((sel & 1) * 8 + rowin) * BROW + (wn * 64 + (sel >> 1) * 8) * 2;

    float acc[2][8][4];
    #pragma unroll
    for (int i = 0; i < 2; i++)
        #pragma unroll
        for (int j = 0; j < 8; j++)
            #pragma unroll
            for (int q = 0; q < 4; q++) acc[i][j][q] = 0.0f;

    float4 Ab[2][4];
    auto loadA = [&](int h, int buf) {   // k16 half h (0..31)
        #pragma unroll
        for (int q = 0; q < 4; q++)
            Ab[buf][q] = ldg128_cs(Xb + offs[q] + (unsigned)h * 64);
    };

    // ---- prologue: B chunks 0,1 staged; A halves 0,1 in regs ----
    issueB(0);
    issueB(1);
    CP_COMMIT();
    loadA(0, 0);
    loadA(1, 1);
    CP_WAIT0();
    __syncthreads();

    // ---- main loop: 8 chunk-pairs, ONE barrier per pair ----
    #pragma unroll 1
    for (int p = 0; p < NPAIR; ++p) {
        // stage next pair (stages (2p+2)&3,(2p+3)&3: consumed in pair p-1, safe)
        if (p + 1 < NPAIR) { issueB(2 * p + 2); issueB(2 * p + 3); }
        CP_COMMIT();

        #pragma unroll
        for (int h2 = 0; h2 < 4; ++h2) {
            const int h     = 4 * p + h2;             // k16 half index
            const int chunk = 2 * p + (h2 >> 1);
            const int buf   = h & 1;
            const unsigned stg = sb + OFF_BSTG + (unsigned)(chunk & 3) * STAGE_SZ;

            // convert A half h -> fragments, then reuse buffer for h+2
            unsigned Ar[8];
            #pragma unroll
            for (int q = 0; q < 4; q++) {
                __half2 t0 = __floats2half2_rn(Ab[buf][q].x, Ab[buf][q].y);
                __half2 t1 = __floats2half2_rn(Ab[buf][q].z, Ab[buf][q].w);
                Ar[(q >> 1) * 4 + (q & 1)]     = *(unsigned*)&t0;
                Ar[(q >> 1) * 4 + (q & 1) + 2] = *(unsigned*)&t1;
            }
            if (h + 2 < NH) loadA(h + 2, buf);        // distance-2 register prefetch

            const unsigned ab = stg + ldm_l + (unsigned)(h2 & 1) * (16 * BROW);

            // B batch 0: j = 0..3
            unsigned bfr[8];
            LDMX4T(bfr[0], bfr[1], bfr[2], bfr[3], ab);
            LDMX4T(bfr[4], bfr[5], bfr[6], bfr[7], ab + 32);
            #pragma unroll
            for (int i = 0; i < 2; i++)
                #pragma unroll
                for (int j = 0; j < 4; j++)
                    MMA16816(acc[i][j], Ar[i * 4 + 0], Ar[i * 4 + 1], Ar[i * 4 + 2], Ar[i * 4 + 3],
                             bfr[2 * j], bfr[2 * j + 1]);

            // B batch 1: j = 4..7
            LDMX4T(bfr[0], bfr[1], bfr[2], bfr[3], ab + 64);
            LDMX4T(bfr[4], bfr[5], bfr[6], bfr[7], ab + 96);
            #pragma unroll
            for (int i = 0; i < 2; i++)
                #pragma unroll
                for (int j = 0; j < 4; j++)
                    MMA16816(acc[i][j + 4], Ar[i * 4 + 0], Ar[i * 4 + 1], Ar[i * 4 + 2], Ar[i * 4 + 3],
                             bfr[2 * j], bfr[2 * j + 1]);
        }

        CP_WAIT0();          // next pair's B complete
        __syncthreads();     // all warps done with this pair's stages
    }

    // ---- epilogue: acc -> sp[128][132] (overlays B stages; mainloop done) ----
    float* sp = (float*)(smem + OFF_SP);
    #pragma unroll
    for (int i = 0; i < 2; i++)
        #pragma unroll
        for (int j = 0; j < 8; j++) {
            int r = wm * 32 + i * 16 + gid;
            int c = wn * 64 + j * 8 + 2 * tig;
            *(float2*)(sp + r * SP_STRIDE + c)       = make_float2(acc[i][j][0], acc[i][j][1]);
            *(float2*)(sp + (r + 8) * SP_STRIDE + c) = make_float2(acc[i][j][2], acc[i][j][3]);
        }
    __syncthreads();

    // ---- pair compute (float4-vectorized) ----
    const int nb = (int)min((long long)BPC, (long long)NBATCH - tile * BPC);
    float* vbuf = (float*)(smem + OFF_VBUF);
    const float4* b14 = (const float4*)(smem + OFF_SB1);
    const float4* w24 = (const float4*)(smem + OFF_SW2);
    const float bias2 = ((const float*)(smem + OFF_SB2))[0];

    for (int p = tid; p < nb * 45; p += 256) {
        int bb = p / 45, q = p - bb * 45;
        const float4* pi4 = (const float4*)(sp + (bb * NNODE + c_I[q]) * SP_STRIDE);       // pa
        const float4* pj4 = (const float4*)(sp + (bb * NNODE + c_J[q]) * SP_STRIDE + HD);  // pb
        float a2 = 0.0f;
        #pragma unroll
        for (int h4 = 0; h4 < HD / 4; h4++) {
            float4 a = pi4[h4], b = pj4[h4], c = b14[h4], w = w24[h4];
            a2 = fmaf(fmaxf(a.x + b.x + c.x, 0.0f), w.x, a2);
            a2 = fmaf(fmaxf(a.y + b.y + c.y, 0.0f), w.y, a2);
            a2 = fmaf(fmaxf(a.z + b.z + c.z, 0.0f), w.z, a2);
            a2 = fmaf(fmaxf(a.w + b.w + c.w, 0.0f), w.w, a2);
        }
        vbuf[p] = a2 + bias2;
    }
    __syncthreads();

    // ---- symmetric scatter (streaming store: out has no reuse) ----
    for (int o = tid; o < nb * 100; o += 256) {
        int bb = o / 100, cell = o - bb * 100;
        int n1 = cell / 10, n2 = cell % 10;
        float val = 0.0f;
        if (n1 != n2) {
            int i = n1 < n2 ? n1 : n2;
            int j = n1 < n2 ? n2 : n1;
            val = vbuf[bb * 45 + 9 * i - (i * (i - 1)) / 2 + (j - i - 1)];
        }
        asm volatile("st.global.cs.f32 [%0], %1;"
                     :: "l"(out + (tile * BPC + bb) * 100 + cell), "f"(val) : "memory");
    }
}

extern "C" void kernel_launch(void* const* d_in, const int* in_sizes, int n_in,
                              void* d_out, int out_size) {
    const float* X  = (const float*)d_in[0];
    const float* W1 = (const float*)d_in[1];
    const float* b1 = (const float*)d_in[2];
    const float* W2 = (const float*)d_in[3];
    const float* b2 = (const float*)d_in[4];
    float* out = (float*)d_out;

    cudaFuncSetAttribute(gemm_pair_kernel,
                         cudaFuncAttributeMaxDynamicSharedMemorySize, SMEM_BYTES);

    convB_kernel<<<(KD * NC + 255) / 256, 256>>>(W1);
    gemm_pair_kernel<<<NCTA, 256, SMEM_BYTES>>>(X, b1, W2, b2, out);
}

// round 14
// speedup vs baseline: 1.1440x; 1.1440x over previous
#include <cuda_runtime.h>
#include <cuda_fp16.h>

// ---------------- problem constants ----------------
#define NBATCH 65536
#define NNODE  10
#define KD     512
#define HD     64
#define NC     128
#define MROWS  (NBATCH * NNODE)            // 655360
#define BPC    12                          // batches per CTA
#define RPC    120                         // valid rows per CTA
#define NCTA   ((NBATCH + BPC - 1) / BPC)  // 5462
#define NCHUNK 16                          // K chunks of 32
#define NH     32                          // k16 halves

// W1 -> fp16, layout [k_phys][n] with k16-slot permutation baked in (see convB).
__device__ __align__(128) __half g_Bh[KD * NC];

__constant__ int c_I[45] = {0,0,0,0,0,0,0,0,0, 1,1,1,1,1,1,1,1, 2,2,2,2,2,2,2,
                            3,3,3,3,3,3, 4,4,4,4,4, 5,5,5,5, 6,6,6, 7,7, 8};
__constant__ int c_J[45] = {1,2,3,4,5,6,7,8,9, 2,3,4,5,6,7,8,9, 3,4,5,6,7,8,9,
                            4,5,6,7,8,9, 5,6,7,8,9, 6,7,8,9, 7,8,9, 8,9, 9};

// ---------------- smem layout (dynamic) ----------------
#define OFF_SB1   0
#define OFF_SW2   256
#define OFF_SB2   512
#define OFF_BSTG  1024
#define BROW      272
#define STAGE_SZ  (32 * BROW)              // 8704
#define OFF_SP    (OFF_BSTG + 2 * STAGE_SZ)       // 18432
#define SP_STRIDE 132                       // 528B rows: 16B-aligned
#define OFF_VBUF  (OFF_SP + 128 * SP_STRIDE * 4)  // 86016
#define SMEM_BYTES (OFF_VBUF + 540 * 4 + 16)      // 88192

__device__ __forceinline__ unsigned smem_u32(const void* p) {
    unsigned a;
    asm("{ .reg .u64 t; cvta.to.shared.u64 t, %1; cvt.u32.u64 %0, t; }" : "=r"(a) : "l"(p));
    return a;
}
__device__ __forceinline__ void cp16(unsigned dst, const void* src) {
    asm volatile("cp.async.cg.shared.global [%0], [%1], 16;" :: "r"(dst), "l"(src) : "memory");
}
#define CP_COMMIT() asm volatile("cp.async.commit_group;" ::: "memory")
#define CP_WAIT0()  asm volatile("cp.async.wait_group 0;" ::: "memory")

#define LDMX4T(r0, r1, r2, r3, addr) \
    asm volatile("ldmatrix.sync.aligned.m8n8.x4.trans.shared.b16 {%0,%1,%2,%3}, [%4];" \
                 : "=r"(r0), "=r"(r1), "=r"(r2), "=r"(r3) : "r"(addr))

#define MMA16816(d, a0, a1, a2, a3, b0, b1) \
    asm volatile("mma.sync.aligned.m16n8k16.row.col.f32.f16.f16.f32 " \
                 "{%0,%1,%2,%3},{%4,%5,%6,%7},{%8,%9},{%0,%1,%2,%3};" \
                 : "+f"((d)[0]), "+f"((d)[1]), "+f"((d)[2]), "+f"((d)[3]) \
                 : "r"(a0), "r"(a1), "r"(a2), "r"(a3), "r"(b0), "r"(b1))

// streaming LDG.128 with 256B L2 prefetch: pulls halves h..h+3 of the row's
// 256B-aligned block into L2, so subsequent half-chunks hit L2 (~234cyc) not DRAM.
__device__ __forceinline__ float4 ldg128_cs_pf(const void* p) {
    float4 v;
    asm volatile("ld.global.cs.L2::256B.v4.f32 {%0,%1,%2,%3}, [%4];"
                 : "=f"(v.x), "=f"(v.y), "=f"(v.z), "=f"(v.w) : "l"(p));
    return v;
}

// ---------------- kernel 0: W1 -> fp16, [k][n], with k16 permutation ----------------
// A is loaded as float4 at col 4*tig: logical ks (4t..4t+3) occupy mma k-slots
// (2t, 2t+1, 2t+8, 2t+9). B rows stored in matching slot order.
__global__ void convB_kernel(const float* __restrict__ W1) {
    int idx = blockIdx.x * 256 + threadIdx.x;      // logical k*128 + n
    if (idx >= KD * NC) return;
    int k = idx >> 7, n = idx & 127;
    float w = W1[((long long)k + (n >= HD ? KD : 0)) * HD + (n & (HD - 1))];
    int kk = k & 15, t = kk >> 2, d = kk & 3;
    int phys = (k & ~15) + t * 2 + (d & 1) + ((d >= 2) ? 8 : 0);
    g_Bh[phys * NC + n] = __float2half_rn(w);
}

// ---------------- fused GEMM (A distance-2 reg prefetch + L2 256B hint) ----------------
__global__ __launch_bounds__(256, 2)
void gemm_pair_kernel(const float* __restrict__ X,
                      const float* __restrict__ b1, const float* __restrict__ W2,
                      const float* __restrict__ b2, float* __restrict__ out) {
    extern __shared__ char smem[];
    const unsigned sb = smem_u32(smem);
    const int tid  = threadIdx.x;
    const int warp = tid >> 5;
    const int lane = tid & 31;
    const int wm   = warp & 3;      // 4 M-groups of 32 rows
    const int wn   = warp >> 2;     // 2 N-groups of 64 cols
    const int gid  = lane >> 2;     // 0..7
    const int tig  = lane & 3;      // 0..3
    const long long tile = blockIdx.x;

    if (tid < HD) {
        ((float*)(smem + OFF_SB1))[tid] = b1[tid];
        ((float*)(smem + OFF_SW2))[tid] = W2[tid];
    }
    if (tid == 0) ((float*)(smem + OFF_SB2))[0] = b2[0];

    // ---- A byte offsets (32-bit: X is 1.34GB < 4GB): rows r, r+8, r+16, r+24 ----
    unsigned offs[4];
    {
        long long r0 = tile * RPC + wm * 32 + gid;
        #pragma unroll
        for (int q = 0; q < 4; q++) {
            long long rr = r0 + q * 8;
            if (rr >= MROWS) rr = MROWS - 1;       // per-row tail clamp (rows unused)
            offs[q] = (unsigned)((rr * KD + 4 * tig) * 4);
        }
    }
    const char* Xb = (const char*)X;

    // ---- B cp.async coordinates ----
    const int bk = tid >> 3;                 // 0..31 (phys k row in chunk)
    const int bg = tid & 7;
    const unsigned bdst0 = (unsigned)(bk * BROW + bg * 16);
    const __half* bsrc = g_Bh + bk * NC + bg * 8;

    // ---- ldmatrix lane address (within stage) ----
    const unsigned sel   = lane >> 3;
    const unsigned rowin = lane & 7;
    const unsigned ldm_l = ((sel & 1) * 8 + rowin) * BROW + (wn * 64 + (sel >> 1) * 8) * 2;

    float acc[2][8][4];
    #pragma unroll
    for (int i = 0; i < 2; i++)
        #pragma unroll
        for (int j = 0; j < 8; j++)
            #pragma unroll
            for (int q = 0; q < 4; q++) acc[i][j][q] = 0.0f;

    float4 Ab[2][4];
    auto loadA = [&](int h, int buf) {   // k16 half h (0..31)
        #pragma unroll
        for (int q = 0; q < 4; q++)
            Ab[buf][q] = ldg128_cs_pf(Xb + offs[q] + (unsigned)h * 64);
    };

    // ---- prologue: B chunk 0 staged; A halves 0,1 in regs ----
    cp16(sb + OFF_BSTG + bdst0,       bsrc);
    cp16(sb + OFF_BSTG + bdst0 + 128, bsrc + 64);
    CP_COMMIT();
    loadA(0, 0);
    loadA(1, 1);
    CP_WAIT0();
    __syncthreads();

    // ---- main loop over 16 chunks of k=32 (2 halves each) ----
    #pragma unroll 1
    for (int it = 0; it < NCHUNK; ++it) {
        const unsigned stg = sb + OFF_BSTG + (it & 1) * STAGE_SZ;

        if (it + 1 < NCHUNK) {
            const unsigned nstg = sb + OFF_BSTG + ((it + 1) & 1) * STAGE_SZ;
            const __half* src = bsrc + (it + 1) * 32 * NC;
            cp16(nstg + bdst0,       src);
            cp16(nstg + bdst0 + 128, src + 64);
            CP_COMMIT();
        }

        #pragma unroll
        for (int h2 = 0; h2 < 2; ++h2) {
            const int h = it * 2 + h2;
            const int buf = h & 1;

            // convert A half h -> fragments, then reuse buffer for h+2
            unsigned Ar[8];
            #pragma unroll
            for (int q = 0; q < 4; q++) {
                __half2 t0 = __floats2half2_rn(Ab[buf][q].x, Ab[buf][q].y);
                __half2 t1 = __floats2half2_rn(Ab[buf][q].z, Ab[buf][q].w);
                Ar[(q >> 1) * 4 + (q & 1)]     = *(unsigned*)&t0;
                Ar[(q >> 1) * 4 + (q & 1) + 2] = *(unsigned*)&t1;
            }
            if (h + 2 < NH) loadA(h + 2, buf);    // distance-2 prefetch

            const unsigned ab = stg + ldm_l + (unsigned)h2 * (16 * BROW);

            // B batch 0: j = 0..3
            unsigned bfr[8];
            LDMX4T(bfr[0], bfr[1], bfr[2], bfr[3], ab);
            LDMX4T(bfr[4], bfr[5], bfr[6], bfr[7], ab + 32);
            #pragma unroll
            for (int i = 0; i < 2; i++)
                #pragma unroll
                for (int j = 0; j < 4; j++)
                    MMA16816(acc[i][j], Ar[i * 4 + 0], Ar[i * 4 + 1], Ar[i * 4 + 2], Ar[i * 4 + 3],
                             bfr[2 * j], bfr[2 * j + 1]);

            // B batch 1: j = 4..7
            LDMX4T(bfr[0], bfr[1], bfr[2], bfr[3], ab + 64);
            LDMX4T(bfr[4], bfr[5], bfr[6], bfr[7], ab + 96);
            #pragma unroll
            for (int i = 0; i < 2; i++)
                #pragma unroll
                for (int j = 0; j < 4; j++)
                    MMA16816(acc[i][j + 4], Ar[i * 4 + 0], Ar[i * 4 + 1], Ar[i * 4 + 2], Ar[i * 4 + 3],
                             bfr[2 * j], bfr[2 * j + 1]);
        }
        CP_WAIT0();
        __syncthreads();
    }

    // ---- epilogue: acc -> sp[128][132] ----
    float* sp = (float*)(smem + OFF_SP);
    #pragma unroll
    for (int i = 0; i < 2; i++)
        #pragma unroll
        for (int j = 0; j < 8; j++) {
            int r = wm * 32 + i * 16 + gid;
            int c = wn * 64 + j * 8 + 2 * tig;
            *(float2*)(sp + r * SP_STRIDE + c)       = make_float2(acc[i][j][0], acc[i][j][1]);
            *(float2*)(sp + (r + 8) * SP_STRIDE + c) = make_float2(acc[i][j][2], acc[i][j][3]);
        }
    __syncthreads();

    // ---- pair compute (float4-vectorized) ----
    const int nb = (int)min((long long)BPC, (long long)NBATCH - tile * BPC);
    float* vbuf = (float*)(smem + OFF_VBUF);
    const float4* b14 = (const float4*)(smem + OFF_SB1);
    const float4* w24 = (const float4*)(smem + OFF_SW2);
    const float bias2 = ((const float*)(smem + OFF_SB2))[0];

    for (int p = tid; p < nb * 45; p += 256) {
        int bb = p / 45, q = p - bb * 45;
        const float4* pi4 = (const float4*)(sp + (bb * NNODE + c_I[q]) * SP_STRIDE);       // pa
        const float4* pj4 = (const float4*)(sp + (bb * NNODE + c_J[q]) * SP_STRIDE + HD);  // pb
        float a2 = 0.0f;
        #pragma unroll
        for (int h4 = 0; h4 < HD / 4; h4++) {
            float4 a = pi4[h4], b = pj4[h4], c = b14[h4], w = w24[h4];
            a2 = fmaf(fmaxf(a.x + b.x + c.x, 0.0f), w.x, a2);
            a2 = fmaf(fmaxf(a.y + b.y + c.y, 0.0f), w.y, a2);
            a2 = fmaf(fmaxf(a.z + b.z + c.z, 0.0f), w.z, a2);
            a2 = fmaf(fmaxf(a.w + b.w + c.w, 0.0f), w.w, a2);
        }
        vbuf[p] = a2 + bias2;
    }
    __syncthreads();

    // ---- symmetric scatter ----
    for (int o = tid; o < nb * 100; o += 256) {
        int bb = o / 100, cell = o - bb * 100;
        int n1 = cell / 10, n2 = cell % 10;
        float val = 0.0f;
        if (n1 != n2) {
            int i = n1 < n2 ? n1 : n2;
            int j = n1 < n2 ? n2 : n1;
            val = vbuf[bb * 45 + 9 * i - (i * (i - 1)) / 2 + (j - i - 1)];
        }
        out[(tile * BPC + bb) * 100 + cell] = val;
    }
}

extern "C" void kernel_launch(void* const* d_in, const int* in_sizes, int n_in,
                              void* d_out, int out_size) {
    const float* X  = (const float*)d_in[0];
    const float* W1 = (const float*)d_in[1];
    const float* b1 = (const float*)d_in[2];
    const float* W2 = (const float*)d_in[3];
    const float* b2 = (const float*)d_in[4];
    float* out = (float*)d_out;

    cudaFuncSetAttribute(gemm_pair_kernel,
                         cudaFuncAttributeMaxDynamicSharedMemorySize, SMEM_BYTES);

    convB_kernel<<<(KD * NC + 255) / 256, 256>>>(W1);
    gemm_pair_kernel<<<NCTA, 256, SMEM_BYTES>>>(X, b1, W2, b2, out);
}